// round 1
// baseline (speedup 1.0000x reference)
#include <cuda_runtime.h>
#include <cuda_bf16.h>

#define EMBED_DIM 128
#define MAX_ATOM_TYPE 119
#define TABLE_ELEMS (MAX_ATOM_TYPE * EMBED_DIM)   // 15232 floats = 60928 B

// Warp-per-atom embedding gather.
// Each block builds the fused table T[t][e] = W[e][t] + b[e] in shared memory
// once (W is tiny: 60KB, stays in L2 across all blocks), then streams atoms:
// one warp per atom, each lane writes one float4 (lane*4 .. lane*4+3) ->
// one fully coalesced 512B STG.128 burst per atom row.
__global__ void __launch_bounds__(256, 3)
embed_atom_kernel(const int* __restrict__ atom_type,
                  const float* __restrict__ W,    // [EMBED_DIM, MAX_ATOM_TYPE] row-major
                  const float* __restrict__ b,    // [EMBED_DIM]
                  float4* __restrict__ out,       // [N, EMBED_DIM] viewed as [N*32] float4
                  int n)
{
    __shared__ float table[TABLE_ELEMS];

    // Build table: table[t*128 + e] = W[e*119 + t] + b[e]
    for (int i = threadIdx.x; i < TABLE_ELEMS; i += blockDim.x) {
        int t = i / EMBED_DIM;
        int e = i - t * EMBED_DIM;
        table[i] = __ldg(&W[e * MAX_ATOM_TYPE + t]) + __ldg(&b[e]);
    }
    __syncthreads();

    const int warps_per_block = blockDim.x >> 5;           // 8
    const int warp = threadIdx.x >> 5;
    const int lane = threadIdx.x & 31;
    const int stride = gridDim.x * warps_per_block;

    for (int a = blockIdx.x * warps_per_block + warp; a < n; a += stride) {
        int t = __ldg(&atom_type[a]);                      // broadcast within warp
        // conflict-free LDS.128: lanes read 16B each, consecutive within the row
        float4 v = *reinterpret_cast<const float4*>(&table[t * EMBED_DIM + lane * 4]);
        out[(size_t)a * 32 + lane] = v;                    // coalesced STG.128
    }
}

extern "C" void kernel_launch(void* const* d_in, const int* in_sizes, int n_in,
                              void* d_out, int out_size)
{
    const int*   atom_type = (const int*)d_in[0];
    const float* W         = (const float*)d_in[1];
    const float* b         = (const float*)d_in[2];
    float4*      out       = (float4*)d_out;
    int n = in_sizes[0];

    // Persistent-ish grid: 3 CTAs/SM fit at 60.9KB smem; 148 SMs -> 444 blocks.
    // Table build (15232 loads) amortized over ~2360 atoms per block.
    int blocks = 444;
    embed_atom_kernel<<<blocks, 256>>>(atom_type, W, b, out, n);
}

// round 2
// speedup vs baseline: 1.8091x; 1.8091x over previous
#include <cuda_runtime.h>
#include <cuda_bf16.h>

#define EMBED_DIM 128
#define MAX_ATOM_TYPE 119
#define TABLE_ELEMS (MAX_ATOM_TYPE * EMBED_DIM)   // 15232 floats = 60928 B
#define CHUNK 32                                   // atoms per warp per outer iter

// Warp-per-32-atoms embedding gather.
// Table T[t][e] = W[e][t] + b[e] built once per block in shared memory.
// Each outer iteration: one coalesced 128B LDG of 32 atom indices (lane k
// holds atom base+k), then 32 independent LDS.128 -> STG.128 pairs (index
// distributed by shuffle). Deep ILP hides smem latency; stores saturate LTS.
__global__ void __launch_bounds__(256, 3)
embed_atom_kernel(const int* __restrict__ atom_type,
                  const float* __restrict__ W,    // [EMBED_DIM, MAX_ATOM_TYPE]
                  const float* __restrict__ b,    // [EMBED_DIM]
                  float4* __restrict__ out,       // [N, 32] float4 view
                  int n)
{
    __shared__ float table[TABLE_ELEMS];

    for (int i = threadIdx.x; i < TABLE_ELEMS; i += blockDim.x) {
        int t = i / EMBED_DIM;
        int e = i - t * EMBED_DIM;
        table[i] = __ldg(&W[e * MAX_ATOM_TYPE + t]) + __ldg(&b[e]);
    }
    __syncthreads();

    const int warps_per_block = blockDim.x >> 5;             // 8
    const int warp = threadIdx.x >> 5;
    const int lane = threadIdx.x & 31;
    const int gwarp = blockIdx.x * warps_per_block + warp;
    const int nwarps = gridDim.x * warps_per_block;

    const int nchunks = n >> 5;                              // n / 32 full chunks

    for (int c = gwarp; c < nchunks; c += nwarps) {
        const int base = c << 5;
        // one coalesced 128B load: lane k gets atom_type[base+k]
        int t_lane = __ldg(&atom_type[base + lane]);

        float4* orow = out + (size_t)base * 32 + lane;       // lane's 16B slot

        #pragma unroll
        for (int k = 0; k < CHUNK; k++) {
            int t = __shfl_sync(0xFFFFFFFFu, t_lane, k);
            float4 v = *reinterpret_cast<const float4*>(&table[t * EMBED_DIM + (lane << 2)]);
            orow[(size_t)k * 32] = v;                        // coalesced STG.128
        }
    }

    // tail (n not multiple of 32) — single-atom path
    for (int a = (nchunks << 5) + gwarp; a < n; a += nwarps) {
        int t = __ldg(&atom_type[a]);
        float4 v = *reinterpret_cast<const float4*>(&table[t * EMBED_DIM + (lane << 2)]);
        out[(size_t)a * 32 + lane] = v;
    }
}

extern "C" void kernel_launch(void* const* d_in, const int* in_sizes, int n_in,
                              void* d_out, int out_size)
{
    const int*   atom_type = (const int*)d_in[0];
    const float* W         = (const float*)d_in[1];
    const float* b         = (const float*)d_in[2];
    float4*      out       = (float4*)d_out;
    int n = in_sizes[0];

    int blocks = 444;   // 3 CTAs/SM x 148 SMs
    embed_atom_kernel<<<blocks, 256>>>(atom_type, W, b, out, n);
}

// round 3
// speedup vs baseline: 2.0069x; 1.1093x over previous
#include <cuda_runtime.h>
#include <cuda_bf16.h>

#define EMBED_DIM 128
#define MAX_ATOM_TYPE 119
#define ROW 132                                    // padded row: 528B, 16B-aligned, conflict-free LDS.128
#define TABLE_ELEMS (MAX_ATOM_TYPE * ROW)          // 15708 floats = 62832 B
#define W_ELEMS (EMBED_DIM * MAX_ATOM_TYPE)        // 15232
#define CHUNK 32

// Warp-per-32-atoms embedding gather with fused smem table.
// Table build: coalesced LDG over W (60KB contiguous), transposed scatter into
// padded table rows (t*132+e). Main loop: one coalesced 128B index load per
// warp per 32 atoms, shfl-distributed; per atom a conflict-free LDS.128 of the
// 512B table row + streaming STG.128 (__stcs) to the output row.
__global__ void __launch_bounds__(256, 3)
embed_atom_kernel(const int* __restrict__ atom_type,
                  const float* __restrict__ W,    // [EMBED_DIM, MAX_ATOM_TYPE]
                  const float* __restrict__ b,    // [EMBED_DIM]
                  float4* __restrict__ out,       // [N, 32] float4 view
                  int n)
{
    __shared__ float table[TABLE_ELEMS];

    // Coalesced build: thread reads W[i] (contiguous), scatters to table[t*ROW+e].
    for (int i = threadIdx.x; i < W_ELEMS; i += blockDim.x) {
        int e = i / MAX_ATOM_TYPE;
        int t = i - e * MAX_ATOM_TYPE;
        table[t * ROW + e] = W[i] + __ldg(&b[e]);
    }
    __syncthreads();

    const int warps_per_block = blockDim.x >> 5;             // 8
    const int warp = threadIdx.x >> 5;
    const int lane = threadIdx.x & 31;
    const int gwarp = blockIdx.x * warps_per_block + warp;
    const int nwarps = gridDim.x * warps_per_block;

    const int nchunks = n >> 5;
    const float* lane_tab = table + (lane << 2);             // lane's 16B slot within a row

    for (int c = gwarp; c < nchunks; c += nwarps) {
        const int base = c << 5;
        int t_lane = __ldg(&atom_type[base + lane]);         // one coalesced 128B load

        float4* orow = out + (size_t)base * 32 + lane;

        #pragma unroll
        for (int k = 0; k < CHUNK; k++) {
            int t = __shfl_sync(0xFFFFFFFFu, t_lane, k);
            float4 v = *reinterpret_cast<const float4*>(lane_tab + t * ROW);
            __stcs(&orow[(size_t)k * 32], v);                // streaming STG.128
        }
    }

    // tail (n not multiple of 32)
    for (int a = (nchunks << 5) + gwarp; a < n; a += nwarps) {
        int t = __ldg(&atom_type[a]);
        float4 v = *reinterpret_cast<const float4*>(lane_tab + t * ROW);
        __stcs(&out[(size_t)a * 32 + lane], v);
    }
}

extern "C" void kernel_launch(void* const* d_in, const int* in_sizes, int n_in,
                              void* d_out, int out_size)
{
    const int*   atom_type = (const int*)d_in[0];
    const float* W         = (const float*)d_in[1];
    const float* b         = (const float*)d_in[2];
    float4*      out       = (float4*)d_out;
    int n = in_sizes[0];

    int blocks = 444;   // 3 CTAs/SM (62.8KB smem each) x 148 SMs
    embed_atom_kernel<<<blocks, 256>>>(atom_type, W, b, out, n);
}